// round 6
// baseline (speedup 1.0000x reference)
#include <cuda_runtime.h>

#define NB   4
#define LEN1 32777
#define M1   4097
#define M2   512
#define CH   256

typedef unsigned long long u64;

// ------- static scratch -------
__device__ float g_out1[NB * M1 * CH];
__device__ float g_gt2[NB * M2 * CH];
__device__ float g_gt1_0[NB * CH];
__device__ float g_attn[NB * M1 * 32];     // softmax attn, (b, m, n*4+h)
__device__ float g_rowdot[NB * LEN1 * 4];  // per-row dot with w_att
__device__ float g_sc1[NB];
__device__ float g_sc2[NB * M2];

// ---- f32x2 helpers ----
__device__ __forceinline__ u64 pk2(float v) {
    u64 r; unsigned int u = __float_as_uint(v);
    asm("mov.b64 %0, {%1, %1};" : "=l"(r) : "r"(u));
    return r;
}
__device__ __forceinline__ void unpk2(u64 v, float& lo, float& hi) {
    unsigned int a, b;
    asm("mov.b64 {%0, %1}, %2;" : "=r"(a), "=r"(b) : "l"(v));
    lo = __uint_as_float(a); hi = __uint_as_float(b);
}
#define FMA2(d, a, b) asm("fma.rn.f32x2 %0, %1, %2, %0;" : "+l"(d) : "l"(a), "l"(b))

// --------------------------------------------------------- init / finalize
__global__ void init_kernel() {
    int i = blockIdx.x * 256 + threadIdx.x;
    if (i < NB) g_sc1[i] = 0.f;
    if (i < NB * M2) g_sc2[i] = 0.f;
}
__global__ void finalize_kernel(float* score1, float* score2) {
    int i = blockIdx.x * 256 + threadIdx.x;
    if (i < NB) score1[i] = 1.f - expf(-0.5f * g_sc1[i]);
    if (i < NB * M2) score2[i] = 1.f - expf(-0.5f * g_sc2[i]);
}

// ------------------------------------------------ gt MLP (f32x2, row pairs)
__global__ void __launch_bounds__(256) gt_kernel(
    const float* __restrict__ gt,
    const float* __restrict__ w1, const float* __restrict__ b1,
    const float* __restrict__ w2, const float* __restrict__ b2)
{
    __shared__ float rsT[256][20];
    __shared__ float g1T[256][20];
    int tid = threadIdx.x, r0 = blockIdx.x * 16;

    #pragma unroll
    for (int i = 0; i < 16; i++)
        rsT[tid][i] = gt[(size_t)(r0 + i) * CH + tid];
    __syncthreads();

    u64 acc[8];
    {
        u64 bb = pk2(b1[tid]);
        #pragma unroll
        for (int j = 0; j < 8; j++) acc[j] = bb;
        for (int c = 0; c < CH; c++) {
            u64 w = pk2(w1[c * CH + tid]);
            const ulonglong2* rp = (const ulonglong2*)&rsT[c][0];
            #pragma unroll
            for (int q = 0; q < 4; q++) {
                ulonglong2 a2 = rp[q];
                FMA2(acc[2 * q + 0], a2.x, w);
                FMA2(acc[2 * q + 1], a2.y, w);
            }
        }
    }
    #pragma unroll
    for (int j = 0; j < 8; j++) {
        float lo, hi; unpk2(acc[j], lo, hi);
        g1T[tid][2 * j]     = fmaxf(lo, 0.f);
        g1T[tid][2 * j + 1] = fmaxf(hi, 0.f);
    }
    if ((r0 & 511) == 0)
        g_gt1_0[(r0 >> 9) * CH + tid] = fmaxf(__uint_as_float((unsigned int)acc[0]), 0.f);
    __syncthreads();

    {
        u64 bb = pk2(b2[tid]);
        #pragma unroll
        for (int j = 0; j < 8; j++) acc[j] = bb;
        for (int c = 0; c < CH; c++) {
            u64 w = pk2(w2[c * CH + tid]);
            const ulonglong2* rp = (const ulonglong2*)&g1T[c][0];
            #pragma unroll
            for (int q = 0; q < 4; q++) {
                ulonglong2 a2 = rp[q];
                FMA2(acc[2 * q + 0], a2.x, w);
                FMA2(acc[2 * q + 1], a2.y, w);
            }
        }
    }
    #pragma unroll
    for (int j = 0; j < 8; j++) {
        float lo, hi; unpk2(acc[j], lo, hi);
        g_gt2[(size_t)(r0 + 2 * j)     * CH + tid] = fmaxf(lo, 0.f);
        g_gt2[(size_t)(r0 + 2 * j + 1) * CH + tid] = fmaxf(hi, 0.f);
    }
}

// ------------------------------------- per-row attention dots (streaming)
__global__ void __launch_bounds__(256) rowdot_kernel(
    const float* __restrict__ x, const float* __restrict__ w_att)
{
    __shared__ float wa_s[1024];
    int tid = threadIdx.x;
    *(float4*)&wa_s[tid * 4] = *(const float4*)&w_att[tid * 4];
    __syncthreads();
    int b = blockIdx.y;
    int r = blockIdx.x * 8 + (tid >> 5);
    if (r >= LEN1) return;
    int lane = tid & 31;
    const float* row = x + ((size_t)b * LEN1 + r) * CH;
    float s0 = 0.f, s1 = 0.f, s2 = 0.f, s3 = 0.f;
    #pragma unroll
    for (int j = 0; j < 8; j++) {
        int c = lane + 32 * j;
        float v = row[c];
        float4 w = *(const float4*)&wa_s[c * 4];
        s0 = fmaf(v, w.x, s0); s1 = fmaf(v, w.y, s1);
        s2 = fmaf(v, w.z, s2); s3 = fmaf(v, w.w, s3);
    }
    #pragma unroll
    for (int s = 16; s > 0; s >>= 1) {
        s0 += __shfl_xor_sync(0xffffffff, s0, s);
        s1 += __shfl_xor_sync(0xffffffff, s1, s);
        s2 += __shfl_xor_sync(0xffffffff, s2, s);
        s3 += __shfl_xor_sync(0xffffffff, s3, s);
    }
    if (lane < 4) {
        float v = (lane == 0) ? s0 : (lane == 1) ? s1 : (lane == 2) ? s2 : s3;
        g_rowdot[((size_t)b * LEN1 + r) * 4 + lane] = v;
    }
}

// ------------------------------------------------ softmax over 8 nodes
__global__ void __launch_bounds__(256) attn_softmax_kernel(const float* __restrict__ b_att)
{
    int tid = threadIdx.x, b = blockIdx.y;
    int m = blockIdx.x * 8 + (tid >> 5);
    if (m >= M1) return;
    int lane = tid & 31;
    int h = lane & 3;
    float lg = g_rowdot[((size_t)b * LEN1 + m) * 4 + h]
             + g_rowdot[((size_t)b * LEN1 + 8 * m + 1) * 4 + lane]
             + b_att[h];
    float mx = lg;
    #pragma unroll
    for (int msk = 4; msk <= 16; msk <<= 1)
        mx = fmaxf(mx, __shfl_xor_sync(0xffffffff, mx, msk));
    float e = expf(lg - mx);
    float sum = e;
    #pragma unroll
    for (int msk = 4; msk <= 16; msk <<= 1)
        sum += __shfl_xor_sync(0xffffffff, sum, msk);
    g_attn[((size_t)b * M1 + m) * 32 + lane] = e / sum;
}

// ----------------------------- fused conv (one group per block, f32x2 GEMM)
// 128 threads, P=128 positions. Per-thread tile: 8 positions x 8 outputs.
#define NT 128

__device__ __forceinline__ void load_w64(float (*Bs)[68], const float* __restrict__ base,
                                         int rstride, int tid)
{
    int r = tid >> 1, f = tid & 1;           // 64 rows (outputs), 2 threads/row
    const float* rp = base + (size_t)r * rstride;
    #pragma unroll
    for (int i = 0; i < 8; i++) {
        int kq = (f + i * 2) * 4;
        float4 t = *(const float4*)(rp + kq);
        Bs[kq + 0][r] = t.x; Bs[kq + 1][r] = t.y;
        Bs[kq + 2][r] = t.z; Bs[kq + 3][r] = t.w;
    }
}

template<int P>
__device__ __forceinline__ void mma_node(const float (*As)[P + 8], const float (*Bs)[68],
                                         u64 acc[4][8], int p0, int o0)
{
    #pragma unroll 4
    for (int k = 0; k < 64; k++) {
        ulonglong2 a01 = *(const ulonglong2*)&As[k][p0];
        ulonglong2 a23 = *(const ulonglong2*)&As[k][p0 + 4];
        float4 w0 = *(const float4*)&Bs[k][o0];
        float4 w1 = *(const float4*)&Bs[k][o0 + 32];
        u64 W0 = pk2(w0.x), W1 = pk2(w0.y), W2 = pk2(w0.z), W3 = pk2(w0.w);
        u64 W4 = pk2(w1.x), W5 = pk2(w1.y), W6 = pk2(w1.z), W7 = pk2(w1.w);
        u64 a0 = a01.x, a1 = a01.y, a2 = a23.x, a3 = a23.y;
        FMA2(acc[0][0], a0, W0); FMA2(acc[0][1], a0, W1);
        FMA2(acc[0][2], a0, W2); FMA2(acc[0][3], a0, W3);
        FMA2(acc[0][4], a0, W4); FMA2(acc[0][5], a0, W5);
        FMA2(acc[0][6], a0, W6); FMA2(acc[0][7], a0, W7);
        FMA2(acc[1][0], a1, W0); FMA2(acc[1][1], a1, W1);
        FMA2(acc[1][2], a1, W2); FMA2(acc[1][3], a1, W3);
        FMA2(acc[1][4], a1, W4); FMA2(acc[1][5], a1, W5);
        FMA2(acc[1][6], a1, W6); FMA2(acc[1][7], a1, W7);
        FMA2(acc[2][0], a2, W0); FMA2(acc[2][1], a2, W1);
        FMA2(acc[2][2], a2, W2); FMA2(acc[2][3], a2, W3);
        FMA2(acc[2][4], a2, W4); FMA2(acc[2][5], a2, W5);
        FMA2(acc[2][6], a2, W6); FMA2(acc[2][7], a2, W7);
        FMA2(acc[3][0], a3, W0); FMA2(acc[3][1], a3, W1);
        FMA2(acc[3][2], a3, W2); FMA2(acc[3][3], a3, W3);
        FMA2(acc[3][4], a3, W4); FMA2(acc[3][5], a3, W5);
        FMA2(acc[3][6], a3, W6); FMA2(acc[3][7], a3, W7);
    }
}

template<int P>
__device__ __forceinline__ void mma_src(const float (*As)[P + 8], const float (*Bs)[68],
                                        u64 acc[2][8], int p0h, int o0)
{
    #pragma unroll 4
    for (int k = 0; k < 64; k++) {
        ulonglong2 a01 = *(const ulonglong2*)&As[k][p0h];
        float4 w0 = *(const float4*)&Bs[k][o0];
        float4 w1 = *(const float4*)&Bs[k][o0 + 32];
        u64 W0 = pk2(w0.x), W1 = pk2(w0.y), W2 = pk2(w0.z), W3 = pk2(w0.w);
        u64 W4 = pk2(w1.x), W5 = pk2(w1.y), W6 = pk2(w1.z), W7 = pk2(w1.w);
        u64 a0 = a01.x, a1 = a01.y;
        FMA2(acc[0][0], a0, W0); FMA2(acc[0][1], a0, W1);
        FMA2(acc[0][2], a0, W2); FMA2(acc[0][3], a0, W3);
        FMA2(acc[0][4], a0, W4); FMA2(acc[0][5], a0, W5);
        FMA2(acc[0][6], a0, W6); FMA2(acc[0][7], a0, W7);
        FMA2(acc[1][0], a1, W0); FMA2(acc[1][1], a1, W1);
        FMA2(acc[1][2], a1, W2); FMA2(acc[1][3], a1, W3);
        FMA2(acc[1][4], a1, W4); FMA2(acc[1][5], a1, W5);
        FMA2(acc[1][6], a1, W6); FMA2(acc[1][7], a1, W7);
    }
}

template<int P, int STAGE>
__global__ void __launch_bounds__(NT) conv_fused_kernel(
    const float* __restrict__ x_in,
    const float* __restrict__ w_node, const float* __restrict__ b_node,
    const float* __restrict__ w_src,  const float* __restrict__ b_src,
    float* __restrict__ outp)
{
    constexpr int M  = (STAGE == 1) ? M1 : M2;
    constexpr int LS = (STAGE == 1) ? LEN1 : M1;
    const float* x   = (STAGE == 1) ? x_in : g_out1;
    const float* gtv = (STAGE == 1) ? g_gt1_0 : g_gt2;
    float*       out = (STAGE == 1) ? g_out1 : outp;

    extern __shared__ float smem[];
    float (*As)[P + 8]  = (float(*)[P + 8])smem;
    float (*Bs)[68]     = (float(*)[68])(smem + 64 * (P + 8));
    float (*attn_s)[8]  = (float(*)[8])(smem + 64 * (P + 8) + 64 * 68);
    float (*s_red)[8]   = (float(*)[8])(smem + 64 * (P + 8) + 64 * 68 + P * 8);

    int tid = threadIdx.x;
    int og = tid & 7, pg = tid >> 3;          // 8 og x 16 pg
    int o0 = og * 4;                          // outputs {o0..o0+3, o0+32..o0+35}
    int p0 = pg * 8;                          // positions p0..p0+7 (4 pairs)
    int b  = blockIdx.y, g = blockIdx.z;
    int m0 = blockIdx.x * P;
    int vrows = M - m0; if (vrows > P) vrows = P;
    int c0 = g * 64;

    for (int i = tid; i < P * 8; i += NT) {
        int p = i >> 3, n = i & 7;
        attn_s[p][n] = (p < vrows)
            ? g_attn[((size_t)b * M1 + m0 + p) * 32 + n * 4 + g] : 0.f;
    }

    const float* node_base = x + ((size_t)b * LS + 8 * (size_t)m0 + 1) * CH + c0;
    const float* src_base  = x + ((size_t)b * LS + m0) * CH + c0;

    // node accumulators: 4 position-pairs x 8 outputs
    u64 accN[4][8];
    {
        float4 b0 = *(const float4*)&b_node[c0 + o0];
        float4 b1 = *(const float4*)&b_node[c0 + o0 + 32];
        u64 B[8] = { pk2(b0.x), pk2(b0.y), pk2(b0.z), pk2(b0.w),
                     pk2(b1.x), pk2(b1.y), pk2(b1.z), pk2(b1.w) };
        #pragma unroll
        for (int pp = 0; pp < 4; pp++)
            #pragma unroll
            for (int o = 0; o < 8; o++) accN[pp][o] = B[o];
    }

    // node conv: K = 256 (ci*4 + t), 4 chunks of 64
    for (int kc = 0; kc < 4; kc++) {
        __syncthreads();
        for (int it = tid; it < P * 4; it += NT) {
            int p = it >> 2, t = it & 3;
            bool val = p < vrows;
            float a0 = val ? attn_s[p][2 * t]     : 0.f;
            float a1 = val ? attn_s[p][2 * t + 1] : 0.f;
            const float* r0p = node_base + (size_t)(8 * p + 2 * t) * CH + kc * 16;
            const float* r1p = r0p + CH;
            #pragma unroll
            for (int q = 0; q < 4; q++) {
                float4 v0 = val ? *(const float4*)(r0p + q * 4) : make_float4(0.f,0.f,0.f,0.f);
                float4 v1 = val ? *(const float4*)(r1p + q * 4) : make_float4(0.f,0.f,0.f,0.f);
                As[(q * 4 + 0) * 4 + t][p] = a0 * v0.x + a1 * v1.x;
                As[(q * 4 + 1) * 4 + t][p] = a0 * v0.y + a1 * v1.y;
                As[(q * 4 + 2) * 4 + t][p] = a0 * v0.z + a1 * v1.z;
                As[(q * 4 + 3) * 4 + t][p] = a0 * v0.w + a1 * v1.w;
            }
        }
        load_w64(Bs, w_node + (size_t)c0 * 256 + kc * 64, 256, tid);
        __syncthreads();
        mma_node<P>(As, Bs, accN, p0, o0);
    }

    // src conv: K = 64, built once, consumed in two 4-position halves
    __syncthreads();
    for (int it = tid; it < P * 16; it += NT) {
        int p = it & (P - 1), q = it / P;
        float4 v = (p < vrows) ? *(const float4*)(src_base + (size_t)p * CH + q * 4)
                               : make_float4(0.f, 0.f, 0.f, 0.f);
        As[q * 4 + 0][p] = v.x; As[q * 4 + 1][p] = v.y;
        As[q * 4 + 2][p] = v.z; As[q * 4 + 3][p] = v.w;
    }
    load_w64(Bs, w_src + (size_t)c0 * 64, 64, tid);
    __syncthreads();

    float4 bs0 = *(const float4*)&b_src[c0 + o0];
    float4 bs1 = *(const float4*)&b_src[c0 + o0 + 32];

    for (int half = 0; half < 2; half++) {
        u64 accS[2][8];
        {
            u64 B[8] = { pk2(bs0.x), pk2(bs0.y), pk2(bs0.z), pk2(bs0.w),
                         pk2(bs1.x), pk2(bs1.y), pk2(bs1.z), pk2(bs1.w) };
            #pragma unroll
            for (int pp = 0; pp < 2; pp++)
                #pragma unroll
                for (int o = 0; o < 8; o++) accS[pp][o] = B[o];
        }
        mma_src<P>(As, Bs, accS, p0 + 4 * half, o0);

        // epilogue for pairs 2*half, 2*half+1
        #pragma unroll
        for (int lp = 0; lp < 2; lp++) {
            int pp = 2 * half + lp;
            float nlo[8], nhi[8], slo[8], shi[8];
            #pragma unroll
            for (int o = 0; o < 8; o++) {
                unpk2(accN[pp][o], nlo[o], nhi[o]);
                unpk2(accS[lp][o], slo[o], shi[o]);
            }
            #pragma unroll
            for (int which = 0; which < 2; which++) {
                int mg = m0 + p0 + 2 * pp + which;
                if (mg < M) {
                    float n[8], r[8];
                    #pragma unroll
                    for (int o = 0; o < 8; o++) {
                        float nv = fmaxf(which ? nhi[o] : nlo[o], 0.f);
                        float sv = fmaxf(which ? shi[o] : slo[o], 0.f);
                        n[o] = nv; r[o] = nv + sv;
                    }
                    float* op = &out[((size_t)b * M + mg) * CH + c0];
                    *(float4*)(op + o0)      = make_float4(r[0], r[1], r[2], r[3]);
                    *(float4*)(op + o0 + 32) = make_float4(r[4], r[5], r[6], r[7]);
                    if (STAGE == 2) {
                        const float* gp = &gtv[((size_t)b * M + mg) * CH + c0];
                        float4 g0 = *(const float4*)(gp + o0);
                        float4 g1 = *(const float4*)(gp + o0 + 32);
                        float d, S = 0.f;
                        d = g0.x - n[0]; S += d*d;  d = g0.y - n[1]; S += d*d;
                        d = g0.z - n[2]; S += d*d;  d = g0.w - n[3]; S += d*d;
                        d = g1.x - n[4]; S += d*d;  d = g1.y - n[5]; S += d*d;
                        d = g1.z - n[6]; S += d*d;  d = g1.w - n[7]; S += d*d;
                        s_red[mg - m0][og] = S;
                    } else if (mg == 0) {
                        const float* gp = &gtv[b * CH + c0];
                        float4 g0 = *(const float4*)(gp + o0);
                        float4 g1 = *(const float4*)(gp + o0 + 32);
                        float d, S = 0.f;
                        d = g0.x - n[0]; S += d*d;  d = g0.y - n[1]; S += d*d;
                        d = g0.z - n[2]; S += d*d;  d = g0.w - n[3]; S += d*d;
                        d = g1.x - n[4]; S += d*d;  d = g1.y - n[5]; S += d*d;
                        d = g1.z - n[6]; S += d*d;  d = g1.w - n[7]; S += d*d;
                        atomicAdd(&g_sc1[b], S);
                    }
                }
            }
        }
    }

    if (STAGE == 2) {
        __syncthreads();
        if (tid < P) {
            float S = 0.f;
            #pragma unroll
            for (int o = 0; o < 8; o++) S += s_red[tid][o];
            atomicAdd(&g_sc2[(size_t)b * M2 + m0 + tid], S);
        }
    }
}

extern "C" void kernel_launch(void* const* d_in, const int* in_sizes, int n_in,
                              void* d_out, int out_size)
{
    const float* input  = (const float*)d_in[0];
    const float* gt     = (const float*)d_in[1];
    const float* w_att  = (const float*)d_in[2];
    const float* b_att  = (const float*)d_in[3];
    const float* w_gt1  = (const float*)d_in[4];
    const float* b_gt1  = (const float*)d_in[5];
    const float* w_gt2  = (const float*)d_in[6];
    const float* b_gt2  = (const float*)d_in[7];
    const float* w_agg1 = (const float*)d_in[8];
    const float* b_agg1 = (const float*)d_in[9];
    const float* w_src1 = (const float*)d_in[10];
    const float* b_src1 = (const float*)d_in[11];
    const float* w_agg2 = (const float*)d_in[12];
    const float* b_agg2 = (const float*)d_in[13];
    const float* w_src2 = (const float*)d_in[14];
    const float* b_src2 = (const float*)d_in[15];

    float* out    = (float*)d_out;                 // (B*512, 256)
    float* score1 = out + (size_t)NB * M2 * CH;    // (B,)
    float* score2 = score1 + NB;                   // (B*512,)

    constexpr int P = 128;
    constexpr int SMEM_CONV = (64 * (P + 8) + 64 * 68 + P * 8 + P * 8) * 4;  // 60416 B
    cudaFuncSetAttribute(conv_fused_kernel<P, 1>,
                         cudaFuncAttributeMaxDynamicSharedMemorySize, SMEM_CONV);
    cudaFuncSetAttribute(conv_fused_kernel<P, 2>,
                         cudaFuncAttributeMaxDynamicSharedMemorySize, SMEM_CONV);

    init_kernel<<<(NB * M2 + 255) / 256, 256>>>();
    gt_kernel<<<NB * M2 / 16, 256>>>(gt, w_gt1, b_gt1, w_gt2, b_gt2);
    rowdot_kernel<<<dim3((LEN1 + 7) / 8, NB), 256>>>(input, w_att);
    attn_softmax_kernel<<<dim3((M1 + 7) / 8, NB), 256>>>(b_att);
    conv_fused_kernel<P, 1><<<dim3((M1 + P - 1) / P, NB, 4), NT, SMEM_CONV>>>(
        input, w_agg1, b_agg1, w_src1, b_src1, nullptr);
    conv_fused_kernel<P, 2><<<dim3(M2 / P, NB, 4), NT, SMEM_CONV>>>(
        input, w_agg2, b_agg2, w_src2, b_src2, out);
    finalize_kernel<<<(NB * M2 + 255) / 256, 256>>>(score1, score2);
}

// round 8
// speedup vs baseline: 1.0923x; 1.0923x over previous
#include <cuda_runtime.h>

#define NB   4
#define LEN1 32777
#define M1   4097
#define M2   512
#define CH   256

typedef unsigned long long u64;

// ------- static scratch -------
__device__ float g_out1[NB * M1 * CH];
__device__ float g_gt2[NB * M2 * CH];
__device__ float g_gt1_0[NB * CH];
__device__ float g_attn[NB * M1 * 32];     // softmax attn, (b, m, n*4+h)
__device__ float g_rowdot[NB * LEN1 * 4];  // per-row dot with w_att
__device__ float g_sc1[NB];
__device__ float g_sc2[NB * M2];

// ---- f32x2 helpers ----
__device__ __forceinline__ u64 pk2(float v) {
    u64 r; unsigned int u = __float_as_uint(v);
    asm("mov.b64 %0, {%1, %1};" : "=l"(r) : "r"(u));
    return r;
}
__device__ __forceinline__ void unpk2(u64 v, float& lo, float& hi) {
    unsigned int a, b;
    asm("mov.b64 {%0, %1}, %2;" : "=r"(a), "=r"(b) : "l"(v));
    lo = __uint_as_float(a); hi = __uint_as_float(b);
}
#define FMA2(d, a, b) asm("fma.rn.f32x2 %0, %1, %2, %0;" : "+l"(d) : "l"(a), "l"(b))

// --------------------------------------------------------- finalize
__global__ void finalize_kernel(float* score1, float* score2) {
    int i = blockIdx.x * 256 + threadIdx.x;
    if (i < NB) score1[i] = 1.f - expf(-0.5f * g_sc1[i]);
    if (i < NB * M2) score2[i] = 1.f - expf(-0.5f * g_sc2[i]);
}

// ------------------------------------------------ gt MLP (f32x2, row pairs)
__global__ void __launch_bounds__(256) gt_kernel(
    const float* __restrict__ gt,
    const float* __restrict__ w1, const float* __restrict__ b1,
    const float* __restrict__ w2, const float* __restrict__ b2)
{
    __shared__ float rsT[256][20];
    __shared__ float g1T[256][20];
    int tid = threadIdx.x, r0 = blockIdx.x * 16;

    #pragma unroll
    for (int i = 0; i < 16; i++)
        rsT[tid][i] = gt[(size_t)(r0 + i) * CH + tid];
    __syncthreads();

    u64 acc[8];
    {
        u64 bb = pk2(b1[tid]);
        #pragma unroll
        for (int j = 0; j < 8; j++) acc[j] = bb;
        for (int c = 0; c < CH; c++) {
            u64 w = pk2(w1[c * CH + tid]);
            const ulonglong2* rp = (const ulonglong2*)&rsT[c][0];
            #pragma unroll
            for (int q = 0; q < 4; q++) {
                ulonglong2 a2 = rp[q];
                FMA2(acc[2 * q + 0], a2.x, w);
                FMA2(acc[2 * q + 1], a2.y, w);
            }
        }
    }
    #pragma unroll
    for (int j = 0; j < 8; j++) {
        float lo, hi; unpk2(acc[j], lo, hi);
        g1T[tid][2 * j]     = fmaxf(lo, 0.f);
        g1T[tid][2 * j + 1] = fmaxf(hi, 0.f);
    }
    if ((r0 & 511) == 0)
        g_gt1_0[(r0 >> 9) * CH + tid] = fmaxf(__uint_as_float((unsigned int)acc[0]), 0.f);
    __syncthreads();

    {
        u64 bb = pk2(b2[tid]);
        #pragma unroll
        for (int j = 0; j < 8; j++) acc[j] = bb;
        for (int c = 0; c < CH; c++) {
            u64 w = pk2(w2[c * CH + tid]);
            const ulonglong2* rp = (const ulonglong2*)&g1T[c][0];
            #pragma unroll
            for (int q = 0; q < 4; q++) {
                ulonglong2 a2 = rp[q];
                FMA2(acc[2 * q + 0], a2.x, w);
                FMA2(acc[2 * q + 1], a2.y, w);
            }
        }
    }
    #pragma unroll
    for (int j = 0; j < 8; j++) {
        float lo, hi; unpk2(acc[j], lo, hi);
        g_gt2[(size_t)(r0 + 2 * j)     * CH + tid] = fmaxf(lo, 0.f);
        g_gt2[(size_t)(r0 + 2 * j + 1) * CH + tid] = fmaxf(hi, 0.f);
    }
}

// ------------------------------------- per-row attention dots (streaming)
__global__ void __launch_bounds__(256) rowdot_kernel(
    const float* __restrict__ x, const float* __restrict__ w_att)
{
    __shared__ float wa_s[1024];
    int tid = threadIdx.x;
    *(float4*)&wa_s[tid * 4] = *(const float4*)&w_att[tid * 4];
    __syncthreads();
    int b = blockIdx.y;
    int r = blockIdx.x * 8 + (tid >> 5);
    if (r >= LEN1) return;
    int lane = tid & 31;
    const float* row = x + ((size_t)b * LEN1 + r) * CH;
    float s0 = 0.f, s1 = 0.f, s2 = 0.f, s3 = 0.f;
    #pragma unroll
    for (int j = 0; j < 8; j++) {
        int c = lane + 32 * j;
        float v = row[c];
        float4 w = *(const float4*)&wa_s[c * 4];
        s0 = fmaf(v, w.x, s0); s1 = fmaf(v, w.y, s1);
        s2 = fmaf(v, w.z, s2); s3 = fmaf(v, w.w, s3);
    }
    #pragma unroll
    for (int s = 16; s > 0; s >>= 1) {
        s0 += __shfl_xor_sync(0xffffffff, s0, s);
        s1 += __shfl_xor_sync(0xffffffff, s1, s);
        s2 += __shfl_xor_sync(0xffffffff, s2, s);
        s3 += __shfl_xor_sync(0xffffffff, s3, s);
    }
    if (lane < 4) {
        float v = (lane == 0) ? s0 : (lane == 1) ? s1 : (lane == 2) ? s2 : s3;
        g_rowdot[((size_t)b * LEN1 + r) * 4 + lane] = v;
    }
}

// ------------------------- softmax over 8 nodes + score-accumulator init
__global__ void __launch_bounds__(256) attn_softmax_kernel(const float* __restrict__ b_att)
{
    int tid = threadIdx.x, b = blockIdx.y;
    int m = blockIdx.x * 8 + (tid >> 5);
    // fold score-accumulator zeroing in (grid.x covers >= M2/8 blocks)
    if (blockIdx.x == 0 && tid == 0) g_sc1[b] = 0.f;
    int zi = blockIdx.x * 256 + tid;
    if (zi < M2) g_sc2[(size_t)b * M2 + zi] = 0.f;
    if (m >= M1) return;
    int lane = tid & 31;
    int h = lane & 3;
    float lg = g_rowdot[((size_t)b * LEN1 + m) * 4 + h]
             + g_rowdot[((size_t)b * LEN1 + 8 * m + 1) * 4 + lane]
             + b_att[h];
    float mx = lg;
    #pragma unroll
    for (int msk = 4; msk <= 16; msk <<= 1)
        mx = fmaxf(mx, __shfl_xor_sync(0xffffffff, mx, msk));
    float e = expf(lg - mx);
    float sum = e;
    #pragma unroll
    for (int msk = 4; msk <= 16; msk <<= 1)
        sum += __shfl_xor_sync(0xffffffff, sum, msk);
    g_attn[((size_t)b * M1 + m) * 32 + lane] = e / sum;
}

// ----------------------------- fused conv (one group per block, f32x2 GEMM)
// 256 threads, P=128. Per-thread tile: 4 positions x 8 outputs
// + register prefetch pipeline: next chunk's LDGs issue during current mma.
#define NT 256

__device__ __forceinline__ void load_w64(float (*Bs)[68], const float* __restrict__ base,
                                         int rstride, int tid)
{
    int r = tid >> 2, f = tid & 3;            // 64 rows (outputs), 4 threads/row
    const float* rp = base + (size_t)r * rstride;
    #pragma unroll
    for (int i = 0; i < 4; i++) {
        int kq = (f + i * 4) * 4;
        float4 t = *(const float4*)(rp + kq);
        Bs[kq + 0][r] = t.x; Bs[kq + 1][r] = t.y;
        Bs[kq + 2][r] = t.z; Bs[kq + 3][r] = t.w;
    }
}

template<int P>
__device__ __forceinline__ void mma_block(const float (*As)[P + 8], const float (*Bs)[68],
                                          u64 acc[4][4], int p0, int o0)
{
    #pragma unroll 8
    for (int k = 0; k < 64; k++) {
        float4 av = *(const float4*)&As[k][p0];
        ulonglong2 w0 = *(const ulonglong2*)&Bs[k][o0];
        ulonglong2 w1 = *(const ulonglong2*)&Bs[k][o0 + 32];
        u64 ap0 = pk2(av.x), ap1 = pk2(av.y), ap2 = pk2(av.z), ap3 = pk2(av.w);
        FMA2(acc[0][0], w0.x, ap0); FMA2(acc[0][1], w0.y, ap0);
        FMA2(acc[0][2], w1.x, ap0); FMA2(acc[0][3], w1.y, ap0);
        FMA2(acc[1][0], w0.x, ap1); FMA2(acc[1][1], w0.y, ap1);
        FMA2(acc[1][2], w1.x, ap1); FMA2(acc[1][3], w1.y, ap1);
        FMA2(acc[2][0], w0.x, ap2); FMA2(acc[2][1], w0.y, ap2);
        FMA2(acc[2][2], w1.x, ap2); FMA2(acc[2][3], w1.y, ap2);
        FMA2(acc[3][0], w0.x, ap3); FMA2(acc[3][1], w0.y, ap3);
        FMA2(acc[3][2], w1.x, ap3); FMA2(acc[3][3], w1.y, ap3);
    }
}

template<int P, int STAGE>
__global__ void __launch_bounds__(NT, 2) conv_fused_kernel(
    const float* __restrict__ x_in,
    const float* __restrict__ w_node, const float* __restrict__ b_node,
    const float* __restrict__ w_src,  const float* __restrict__ b_src,
    float* __restrict__ outp)
{
    constexpr int M  = (STAGE == 1) ? M1 : M2;
    constexpr int LS = (STAGE == 1) ? LEN1 : M1;
    const float* x   = (STAGE == 1) ? x_in : g_out1;
    const float* gtv = (STAGE == 1) ? g_gt1_0 : g_gt2;
    float*       out = (STAGE == 1) ? g_out1 : outp;

    extern __shared__ float smem[];
    float (*As)[P + 8]  = (float(*)[P + 8])smem;
    float (*Bs)[68]     = (float(*)[68])(smem + 64 * (P + 8));
    float (*attn_s)[8]  = (float(*)[8])(smem + 64 * (P + 8) + 64 * 68);
    float (*s_red)[8]   = (float(*)[8])(smem + 64 * (P + 8) + 64 * 68 + P * 8);

    int tid = threadIdx.x;
    int og = tid & 7, pg = tid >> 3;          // 8 og x 32 pg
    int o0 = og * 4;                          // outputs {o0..o0+3, o0+32..o0+35}
    int p0 = pg * 4;                          // positions p0..p0+3
    int b  = blockIdx.y, g = blockIdx.z;
    int m0 = blockIdx.x * P;
    int vrows = M - m0; if (vrows > P) vrows = P;
    int c0 = g * 64;

    for (int i = tid; i < P * 8; i += NT) {
        int p = i >> 3, n = i & 7;
        attn_s[p][n] = (p < vrows)
            ? g_attn[((size_t)b * M1 + m0 + p) * 32 + n * 4 + g] : 0.f;
    }
    __syncthreads();

    const float* node_base = x + ((size_t)b * LS + 8 * (size_t)m0 + 1) * CH + c0;
    const float* src_base  = x + ((size_t)b * LS + m0) * CH + c0;

    u64 accN[4][4], accS[4][4];
    {
        ulonglong2 bn0 = *(const ulonglong2*)&b_node[c0 + o0];
        ulonglong2 bn1 = *(const ulonglong2*)&b_node[c0 + o0 + 32];
        ulonglong2 bs0 = *(const ulonglong2*)&b_src[c0 + o0];
        ulonglong2 bs1 = *(const ulonglong2*)&b_src[c0 + o0 + 32];
        #pragma unroll
        for (int p = 0; p < 4; p++) {
            accN[p][0] = bn0.x; accN[p][1] = bn0.y; accN[p][2] = bn1.x; accN[p][3] = bn1.y;
            accS[p][0] = bs0.x; accS[p][1] = bs0.y; accS[p][2] = bs1.x; accS[p][3] = bs1.y;
        }
    }

    // prefetch registers: node uses pv0/pv1 [2][4]; src reuses flat pv0 (8 float4)
    float4 pv0[2][4], pv1[2][4];

    #define PREFETCH_NODE(kc)                                                     \
        { _Pragma("unroll")                                                       \
          for (int u = 0; u < 2; u++) {                                           \
            int it = tid + u * NT;                                                \
            int p = it >> 2, t = it & 3;                                          \
            bool val = p < vrows;                                                 \
            const float* r0p = node_base + (size_t)(8 * p + 2 * t) * CH + (kc) * 16; \
            const float* r1p = r0p + CH;                                          \
            _Pragma("unroll")                                                     \
            for (int q = 0; q < 4; q++) {                                         \
                pv0[u][q] = val ? *(const float4*)(r0p + q * 4) : make_float4(0.f,0.f,0.f,0.f); \
                pv1[u][q] = val ? *(const float4*)(r1p + q * 4) : make_float4(0.f,0.f,0.f,0.f); \
            }                                                                     \
          } }

    PREFETCH_NODE(0);

    for (int kc = 0; kc < 4; kc++) {
        __syncthreads();                       // previous mma done with As/Bs
        #pragma unroll
        for (int u = 0; u < 2; u++) {
            int it = tid + u * NT;
            int p = it >> 2, t = it & 3;
            bool val = p < vrows;
            float a0 = val ? attn_s[p][2 * t]     : 0.f;
            float a1 = val ? attn_s[p][2 * t + 1] : 0.f;
            #pragma unroll
            for (int q = 0; q < 4; q++) {
                As[(q * 4 + 0) * 4 + t][p] = a0 * pv0[u][q].x + a1 * pv1[u][q].x;
                As[(q * 4 + 1) * 4 + t][p] = a0 * pv0[u][q].y + a1 * pv1[u][q].y;
                As[(q * 4 + 2) * 4 + t][p] = a0 * pv0[u][q].z + a1 * pv1[u][q].z;
                As[(q * 4 + 3) * 4 + t][p] = a0 * pv0[u][q].w + a1 * pv1[u][q].w;
            }
        }
        load_w64(Bs, w_node + (size_t)c0 * 256 + kc * 64, 256, tid);
        __syncthreads();
        if (kc < 3) {
            PREFETCH_NODE(kc + 1);             // LDGs fly during mma below
        } else {
            // prefetch src tile (8 float4) during the last node mma
            #pragma unroll
            for (int u = 0; u < 8; u++) {
                int it = tid + u * NT;
                int p = it & (P - 1);
                int q = it / P;
                float4 v = (p < vrows) ? *(const float4*)(src_base + (size_t)p * CH + q * 4)
                                       : make_float4(0.f, 0.f, 0.f, 0.f);
                ((float4*)pv0)[u] = v;
            }
        }
        mma_block<P>(As, Bs, accN, p0, o0);
    }

    // src conv: K = 64 (data already in pv0 flat view)
    __syncthreads();
    #pragma unroll
    for (int u = 0; u < 8; u++) {
        int it = tid + u * NT;
        int p = it & (P - 1);
        int q = it / P;
        float4 v = ((float4*)pv0)[u];
        As[q * 4 + 0][p] = v.x; As[q * 4 + 1][p] = v.y;
        As[q * 4 + 2][p] = v.z; As[q * 4 + 3][p] = v.w;
    }
    load_w64(Bs, w_src + (size_t)c0 * 64, 64, tid);
    __syncthreads();
    mma_block<P>(As, Bs, accS, p0, o0);

    // epilogue
    #pragma unroll
    for (int pi = 0; pi < 4; pi++) {
        int mg = m0 + p0 + pi;
        float n[8], s[8];
        unpk2(accN[pi][0], n[0], n[1]); unpk2(accN[pi][1], n[2], n[3]);
        unpk2(accN[pi][2], n[4], n[5]); unpk2(accN[pi][3], n[6], n[7]);
        unpk2(accS[pi][0], s[0], s[1]); unpk2(accS[pi][1], s[2], s[3]);
        unpk2(accS[pi][2], s[4], s[5]); unpk2(accS[pi][3], s[6], s[7]);
        #pragma unroll
        for (int o = 0; o < 8; o++) { n[o] = fmaxf(n[o], 0.f); s[o] = fmaxf(s[o], 0.f); }
        if (mg < M) {
            float* op = &out[((size_t)b * M + mg) * CH + c0];
            *(float4*)(op + o0)      = make_float4(n[0]+s[0], n[1]+s[1], n[2]+s[2], n[3]+s[3]);
            *(float4*)(op + o0 + 32) = make_float4(n[4]+s[4], n[5]+s[5], n[6]+s[6], n[7]+s[7]);
            if (STAGE == 2) {
                const float* gp = &gtv[((size_t)b * M + mg) * CH + c0];
                float4 g0 = *(const float4*)(gp + o0);
                float4 g1 = *(const float4*)(gp + o0 + 32);
                float d, S = 0.f;
                d = g0.x - n[0]; S += d*d;  d = g0.y - n[1]; S += d*d;
                d = g0.z - n[2]; S += d*d;  d = g0.w - n[3]; S += d*d;
                d = g1.x - n[4]; S += d*d;  d = g1.y - n[5]; S += d*d;
                d = g1.z - n[6]; S += d*d;  d = g1.w - n[7]; S += d*d;
                s_red[p0 + pi][og] = S;
            } else if (mg == 0) {
                const float* gp = &gtv[b * CH + c0];
                float4 g0 = *(const float4*)(gp + o0);
                float4 g1 = *(const float4*)(gp + o0 + 32);
                float d, S = 0.f;
                d = g0.x - n[0]; S += d*d;  d = g0.y - n[1]; S += d*d;
                d = g0.z - n[2]; S += d*d;  d = g0.w - n[3]; S += d*d;
                d = g1.x - n[4]; S += d*d;  d = g1.y - n[5]; S += d*d;
                d = g1.z - n[6]; S += d*d;  d = g1.w - n[7]; S += d*d;
                atomicAdd(&g_sc1[b], S);
            }
        }
    }
    if (STAGE == 2) {
        __syncthreads();
        if (tid < P) {
            float S = 0.f;
            #pragma unroll
            for (int o = 0; o < 8; o++) S += s_red[tid][o];
            atomicAdd(&g_sc2[(size_t)b * M2 + m0 + tid], S);
        }
    }
}

extern "C" void kernel_launch(void* const* d_in, const int* in_sizes, int n_in,
                              void* d_out, int out_size)
{
    const float* input  = (const float*)d_in[0];
    const float* gt     = (const float*)d_in[1];
    const float* w_att  = (const float*)d_in[2];
    const float* b_att  = (const float*)d_in[3];
    const float* w_gt1  = (const float*)d_in[4];
    const float* b_gt1  = (const float*)d_in[5];
    const float* w_gt2  = (const float*)d_in[6];
    const float* b_gt2  = (const float*)d_in[7];
    const float* w_agg1 = (const float*)d_in[8];
    const float* b_agg1 = (const float*)d_in[9];
    const float* w_src1 = (const float*)d_in[10];
    const float* b_src1 = (const float*)d_in[11];
    const float* w_agg2 = (const float*)d_in[12];
    const float* b_agg2 = (const float*)d_in[13];
    const float* w_src2 = (const float*)d_in[14];
    const float* b_src2 = (const float*)d_in[15];

    float* out    = (float*)d_out;                 // (B*512, 256)
    float* score1 = out + (size_t)NB * M2 * CH;    // (B,)
    float* score2 = score1 + NB;                   // (B*512,)

    constexpr int P = 128;
    constexpr int SMEM_CONV = (64 * (P + 8) + 64 * 68 + P * 8 + P * 8) * 4;  // 60416 B
    cudaFuncSetAttribute(conv_fused_kernel<P, 1>,
                         cudaFuncAttributeMaxDynamicSharedMemorySize, SMEM_CONV);
    cudaFuncSetAttribute(conv_fused_kernel<P, 2>,
                         cudaFuncAttributeMaxDynamicSharedMemorySize, SMEM_CONV);

    // conv1 at captured launch index 3 (for ncu -s/-c), dependencies intact:
    // rowdot -> softmax(+score init) -> gt -> conv1 -> conv2 -> finalize
    rowdot_kernel<<<dim3((LEN1 + 7) / 8, NB), 256>>>(input, w_att);
    attn_softmax_kernel<<<dim3((M1 + 7) / 8, NB), 256>>>(b_att);
    gt_kernel<<<NB * M2 / 16, 256>>>(gt, w_gt1, b_gt1, w_gt2, b_gt2);
    conv_fused_kernel<P, 1><<<dim3((M1 + P - 1) / P, NB, 4), NT, SMEM_CONV>>>(
        input, w_agg1, b_agg1, w_src1, b_src1, nullptr);
    conv_fused_kernel<P, 2><<<dim3(M2 / P, NB, 4), NT, SMEM_CONV>>>(
        input, w_agg2, b_agg2, w_src2, b_src2, out);
    finalize_kernel<<<(NB * M2 + 255) / 256, 256>>>(score1, score2);
}